// round 1
// baseline (speedup 1.0000x reference)
#include <cuda_runtime.h>
#include <math.h>

#define B_    8
#define C_    192
#define HW_   16384
#define CHW_  3145728
#define NTOT_ 25165824

// ---------------- device scratch (no allocations allowed) ----------------
__device__ unsigned g_min_enc[B_];
__device__ unsigned g_max_enc[B_];
__device__ float    g_xmin[B_];
__device__ float    g_denom[B_];
__device__ float    g_cw[C_ * 58];   // packed per-channel transformed weights

// monotone float<->uint encoding for atomic min/max
__device__ __forceinline__ unsigned fenc(float f) {
    unsigned u = __float_as_uint(f);
    return (u & 0x80000000u) ? ~u : (u | 0x80000000u);
}
__device__ __forceinline__ float fdec(unsigned u) {
    return (u & 0x80000000u) ? __uint_as_float(u ^ 0x80000000u)
                             : __uint_as_float(~u);
}

// ---------------- kernel 0: init reduction cells ----------------
__global__ void k_init() {
    int t = threadIdx.x;
    if (t < B_) {
        g_min_enc[t] = 0xFFFFFFFFu;
        g_max_enc[t] = 0u;
    }
}

// ---------------- kernel 1: per-sample min/max ----------------
// 2048 blocks (256 per sample), 256 threads, 12288 elems (3072 float4) per block
__global__ void __launch_bounds__(256) k_minmax(const float* __restrict__ x) {
    int s  = blockIdx.x >> 8;
    int jb = blockIdx.x & 255;
    const float4* xp = reinterpret_cast<const float4*>(x + (size_t)s * CHW_) + (size_t)jb * 3072;

    float mn = __int_as_float(0x7f800000);
    float mx = -mn;
    for (int i = threadIdx.x; i < 3072; i += 256) {
        float4 v = xp[i];
        mn = fminf(mn, fminf(fminf(v.x, v.y), fminf(v.z, v.w)));
        mx = fmaxf(mx, fmaxf(fmaxf(v.x, v.y), fmaxf(v.z, v.w)));
    }
    // warp reduce
    #pragma unroll
    for (int o = 16; o > 0; o >>= 1) {
        mn = fminf(mn, __shfl_xor_sync(0xffffffffu, mn, o));
        mx = fmaxf(mx, __shfl_xor_sync(0xffffffffu, mx, o));
    }
    __shared__ float smn[8], smx[8];
    int w = threadIdx.x >> 5, l = threadIdx.x & 31;
    if (l == 0) { smn[w] = mn; smx[w] = mx; }
    __syncthreads();
    if (threadIdx.x == 0) {
        mn = smn[0]; mx = smx[0];
        #pragma unroll
        for (int i = 1; i < 8; i++) { mn = fminf(mn, smn[i]); mx = fmaxf(mx, smx[i]); }
        atomicMin(&g_min_enc[s], fenc(mn));
        atomicMax(&g_max_enc[s], fenc(mx));
    }
}

// ---------------- kernel 2: precompute transformed weights ----------------
// Layout per channel (58 floats):
//  0: W0[3]  3: B0[3]  6: T0[3]
//  9: W1[9] 18: B1[3] 21: T1[3]
// 24: W2[9] 33: B2[3] 36: T2[3]
// 39: W3[9] 48: B3[3] 51: T3[3]
// 54: W4[3] 57: B4[1]
__device__ __forceinline__ float softplus_acc(float v) {
    return fmaxf(v, 0.0f) + log1pf(expf(-fabsf(v)));
}

__global__ void k_prep(const float* __restrict__ m0, const float* __restrict__ b0,
                       const float* __restrict__ m1, const float* __restrict__ b1,
                       const float* __restrict__ m2, const float* __restrict__ b2,
                       const float* __restrict__ m3, const float* __restrict__ b3,
                       const float* __restrict__ m4, const float* __restrict__ b4,
                       const float* __restrict__ f0, const float* __restrict__ f1,
                       const float* __restrict__ f2, const float* __restrict__ f3) {
    int c = threadIdx.x;
    if (c < C_) {
        float* w = &g_cw[c * 58];
        #pragma unroll
        for (int j = 0; j < 3; j++) {
            w[0 + j]  = softplus_acc(m0[c * 3 + j]);
            w[3 + j]  = b0[c * 3 + j];
            w[6 + j]  = tanhf(f0[c * 3 + j]);
            w[18 + j] = b1[c * 3 + j];
            w[21 + j] = tanhf(f1[c * 3 + j]);
            w[33 + j] = b2[c * 3 + j];
            w[36 + j] = tanhf(f2[c * 3 + j]);
            w[48 + j] = b3[c * 3 + j];
            w[51 + j] = tanhf(f3[c * 3 + j]);
            w[54 + j] = softplus_acc(m4[c * 3 + j]);
        }
        #pragma unroll
        for (int j = 0; j < 9; j++) {
            w[9  + j] = softplus_acc(m1[c * 9 + j]);
            w[24 + j] = softplus_acc(m2[c * 9 + j]);
            w[39 + j] = softplus_acc(m3[c * 9 + j]);
        }
        w[57] = b4[c];
    }
    if (threadIdx.x < B_) {
        int s = threadIdx.x;
        float mn = fdec(g_min_enc[s]);
        float mx = fdec(g_max_enc[s]);
        g_xmin[s]  = mn;
        g_denom[s] = (mx - mn) + 1e-12f;
    }
}

// ---------------- main kernel ----------------
// accurate tanh: 1 - 2/(e^{2x}+1); abs err ~1e-6 (cancellation at small x is
// absolute-error-benign since gates use additive t*tanh(y))
__device__ __forceinline__ float tanh_acc(float v) {
    float e = __expf(v + v);
    return 1.0f - __fdividef(2.0f, e + 1.0f);
}
__device__ __forceinline__ float sigf(float v) {
    return __fdividef(1.0f, 1.0f + __expf(-v));
}

__device__ __forceinline__ float mlp_eval(float v, const float* w) {
    float y0 = fmaf(w[0], v, w[3]);
    float y1 = fmaf(w[1], v, w[4]);
    float y2 = fmaf(w[2], v, w[5]);
    y0 = fmaf(w[6], tanh_acc(y0), y0);
    y1 = fmaf(w[7], tanh_acc(y1), y1);
    y2 = fmaf(w[8], tanh_acc(y2), y2);
    #pragma unroll
    for (int L = 0; L < 3; L++) {
        int WO = 9 + L * 15, BO = WO + 9, TO = WO + 12;
        float z0 = fmaf(w[WO + 0], y0, fmaf(w[WO + 1], y1, fmaf(w[WO + 2], y2, w[BO + 0])));
        float z1 = fmaf(w[WO + 3], y0, fmaf(w[WO + 4], y1, fmaf(w[WO + 5], y2, w[BO + 1])));
        float z2 = fmaf(w[WO + 6], y0, fmaf(w[WO + 7], y1, fmaf(w[WO + 8], y2, w[BO + 2])));
        y0 = fmaf(w[TO + 0], tanh_acc(z0), z0);
        y1 = fmaf(w[TO + 1], tanh_acc(z1), z1);
        y2 = fmaf(w[TO + 2], tanh_acc(z2), z2);
    }
    return fmaf(w[54], y0, fmaf(w[55], y1, fmaf(w[56], y2, w[57])));
}

// 12288 blocks x 256 threads x 8 elements; each block covers 2048 contiguous
// elements of a single (b,c) plane (2048 | 16384), so channel is block-uniform.
__global__ void __launch_bounds__(256) k_main(const float* __restrict__ x,
                                              float* __restrict__ out) {
    const int base = blockIdx.x * 2048;
    const int c = (base >> 14) % C_;
    const int s = base / CHW_;

    float w[58];
    const float* cw = g_cw + c * 58;
    #pragma unroll
    for (int i = 0; i < 58; i++) w[i] = __ldg(cw + i);

    const float xmin  = g_xmin[s];
    const float denom = g_denom[s];
    float* __restrict__ outL = out + NTOT_;
    const int t = threadIdx.x;

    float xv[8];
    #pragma unroll
    for (int k = 0; k < 8; k++) xv[k] = __ldg(x + base + t + k * 256);

    #pragma unroll 2
    for (int k = 0; k < 8; k++) {
        int idx = base + t + k * 256;
        // bit-exact replication of reference quantization arithmetic
        float q  = rintf(__fdiv_rn(__fmul_rn(__fsub_rn(xv[k], xmin), 65535.0f), denom));
        float xd = __fdiv_rn(q, 65535.0f);
        out[idx] = xd;
        float lg = mlp_eval(xd - 0.5f, w);
        float ug = mlp_eval(xd + 0.5f, w);
        float lik = fmaxf(sigf(ug) - sigf(lg), 1e-9f);
        outL[idx] = lik;
    }
}

// ---------------- host launcher ----------------
extern "C" void kernel_launch(void* const* d_in, const int* in_sizes, int n_in,
                              void* d_out, int out_size) {
    const float* x = (const float*)d_in[0];
    const float *m[5], *bb[5], *ff[4];
    if (n_in >= 15 && in_sizes[2] == 1728) {
        // signature order: x, m0..m4, b0..b4, f0..f3
        for (int i = 0; i < 5; i++) { m[i]  = (const float*)d_in[1 + i];
                                      bb[i] = (const float*)d_in[6 + i]; }
        for (int i = 0; i < 4; i++)   ff[i] = (const float*)d_in[11 + i];
    } else {
        // dict insertion order: x, m0, b0, m1, b1, ..., m4, b4, f0..f3
        for (int i = 0; i < 5; i++) { m[i]  = (const float*)d_in[1 + 2 * i];
                                      bb[i] = (const float*)d_in[2 + 2 * i]; }
        for (int i = 0; i < 4; i++)   ff[i] = (const float*)d_in[11 + i];
    }
    float* out = (float*)d_out;

    k_init<<<1, 32>>>();
    k_minmax<<<2048, 256>>>(x);
    k_prep<<<1, 192>>>(m[0], bb[0], m[1], bb[1], m[2], bb[2], m[3], bb[3],
                       m[4], bb[4], ff[0], ff[1], ff[2], ff[3]);
    k_main<<<12288, 256>>>(x, out);
}

// round 2
// speedup vs baseline: 1.3660x; 1.3660x over previous
#include <cuda_runtime.h>
#include <math.h>

#define B_    8
#define C_    192
#define HW_   16384
#define CHW_  3145728
#define NTOT_ 25165824
#define NQ_   65536

// ---------------- device scratch (no allocations allowed) ----------------
__device__ unsigned g_min_enc[B_];
__device__ unsigned g_max_enc[B_];
__device__ float    g_qs[B_];          // per-sample quantize scale
__device__ float    g_qo[B_];          // per-sample quantize offset
__device__ float    g_cw[C_ * 58];     // packed per-channel transformed weights
__device__ float    g_xd[NQ_];         // dequantized value per q
__device__ float    g_lik[C_ * NQ_];   // likelihood table (c, q)  ~50MB

// monotone float<->uint encoding for atomic min/max
__device__ __forceinline__ unsigned fenc(float f) {
    unsigned u = __float_as_uint(f);
    return (u & 0x80000000u) ? ~u : (u | 0x80000000u);
}
__device__ __forceinline__ float fdec(unsigned u) {
    return (u & 0x80000000u) ? __uint_as_float(u ^ 0x80000000u)
                             : __uint_as_float(~u);
}

// ---------------- kernel 0: init reduction cells ----------------
__global__ void k_init() {
    int t = threadIdx.x;
    if (t < B_) {
        g_min_enc[t] = 0xFFFFFFFFu;
        g_max_enc[t] = 0u;
    }
}

// ---------------- kernel 1: per-sample min/max ----------------
__global__ void __launch_bounds__(256) k_minmax(const float* __restrict__ x) {
    int s  = blockIdx.x >> 8;
    int jb = blockIdx.x & 255;
    const float4* xp = reinterpret_cast<const float4*>(x + (size_t)s * CHW_) + (size_t)jb * 3072;

    float mn = __int_as_float(0x7f800000);
    float mx = -mn;
    for (int i = threadIdx.x; i < 3072; i += 256) {
        float4 v = xp[i];
        mn = fminf(mn, fminf(fminf(v.x, v.y), fminf(v.z, v.w)));
        mx = fmaxf(mx, fmaxf(fmaxf(v.x, v.y), fmaxf(v.z, v.w)));
    }
    #pragma unroll
    for (int o = 16; o > 0; o >>= 1) {
        mn = fminf(mn, __shfl_xor_sync(0xffffffffu, mn, o));
        mx = fmaxf(mx, __shfl_xor_sync(0xffffffffu, mx, o));
    }
    __shared__ float smn[8], smx[8];
    int w = threadIdx.x >> 5, l = threadIdx.x & 31;
    if (l == 0) { smn[w] = mn; smx[w] = mx; }
    __syncthreads();
    if (threadIdx.x == 0) {
        mn = smn[0]; mx = smx[0];
        #pragma unroll
        for (int i = 1; i < 8; i++) { mn = fminf(mn, smn[i]); mx = fmaxf(mx, smx[i]); }
        atomicMin(&g_min_enc[s], fenc(mn));
        atomicMax(&g_max_enc[s], fenc(mx));
    }
}

// ---------------- kernel 2: precompute transformed weights ----------------
__device__ __forceinline__ float softplus_acc(float v) {
    return fmaxf(v, 0.0f) + log1pf(expf(-fabsf(v)));
}

__global__ void k_prep(const float* __restrict__ m0, const float* __restrict__ b0,
                       const float* __restrict__ m1, const float* __restrict__ b1,
                       const float* __restrict__ m2, const float* __restrict__ b2,
                       const float* __restrict__ m3, const float* __restrict__ b3,
                       const float* __restrict__ m4, const float* __restrict__ b4,
                       const float* __restrict__ f0, const float* __restrict__ f1,
                       const float* __restrict__ f2, const float* __restrict__ f3) {
    int c = threadIdx.x;
    if (c < C_) {
        float* w = &g_cw[c * 58];
        #pragma unroll
        for (int j = 0; j < 3; j++) {
            w[0 + j]  = softplus_acc(m0[c * 3 + j]);
            w[3 + j]  = b0[c * 3 + j];
            w[6 + j]  = tanhf(f0[c * 3 + j]);
            w[18 + j] = b1[c * 3 + j];
            w[21 + j] = tanhf(f1[c * 3 + j]);
            w[33 + j] = b2[c * 3 + j];
            w[36 + j] = tanhf(f2[c * 3 + j]);
            w[48 + j] = b3[c * 3 + j];
            w[51 + j] = tanhf(f3[c * 3 + j]);
            w[54 + j] = softplus_acc(m4[c * 3 + j]);
        }
        #pragma unroll
        for (int j = 0; j < 9; j++) {
            w[9  + j] = softplus_acc(m1[c * 9 + j]);
            w[24 + j] = softplus_acc(m2[c * 9 + j]);
            w[39 + j] = softplus_acc(m3[c * 9 + j]);
        }
        w[57] = b4[c];
    }
    if (threadIdx.x < B_) {
        int s = threadIdx.x;
        float mn = fdec(g_min_enc[s]);
        float mx = fdec(g_max_enc[s]);
        float denom = (mx - mn) + 1e-12f;
        float qs = __fdiv_rn(65535.0f, denom);   // q = rint((x - mn) * qs)
        g_qs[s] = qs;
        g_qo[s] = -mn * qs;
    }
}

// ---------------- MLP with approx tanh gates, accurate final sigmoid ----------
__device__ __forceinline__ float tanha(float v) {
    float r;
    asm("tanh.approx.f32 %0, %1;" : "=f"(r) : "f"(v));
    return r;
}
__device__ __forceinline__ float sigf(float v) {
    return __fdividef(1.0f, 1.0f + __expf(-v));
}

__device__ __forceinline__ float mlp_eval(float v, const float* w) {
    float y0 = fmaf(w[0], v, w[3]);
    float y1 = fmaf(w[1], v, w[4]);
    float y2 = fmaf(w[2], v, w[5]);
    y0 = fmaf(w[6], tanha(y0), y0);
    y1 = fmaf(w[7], tanha(y1), y1);
    y2 = fmaf(w[8], tanha(y2), y2);
    #pragma unroll
    for (int L = 0; L < 3; L++) {
        int WO = 9 + L * 15, BO = WO + 9, TO = WO + 12;
        float z0 = fmaf(w[WO + 0], y0, fmaf(w[WO + 1], y1, fmaf(w[WO + 2], y2, w[BO + 0])));
        float z1 = fmaf(w[WO + 3], y0, fmaf(w[WO + 4], y1, fmaf(w[WO + 5], y2, w[BO + 1])));
        float z2 = fmaf(w[WO + 6], y0, fmaf(w[WO + 7], y1, fmaf(w[WO + 8], y2, w[BO + 2])));
        y0 = fmaf(w[TO + 0], tanha(z0), z0);
        y1 = fmaf(w[TO + 1], tanha(z1), z1);
        y2 = fmaf(w[TO + 2], tanha(z2), z2);
    }
    return fmaf(w[54], y0, fmaf(w[55], y1, fmaf(w[56], y2, w[57])));
}

// ---------------- kernel 3: build (c, q) likelihood table ----------------
// 192*32 = 6144 blocks x 256 threads x 8 q's
__global__ void __launch_bounds__(256) k_table() {
    const int c  = blockIdx.x >> 5;
    const int q0 = ((blockIdx.x & 31) << 11) + threadIdx.x;

    float w[58];
    const float* cw = g_cw + c * 58;
    #pragma unroll
    for (int i = 0; i < 58; i++) w[i] = __ldg(cw + i);

    float* lt = g_lik + (size_t)c * NQ_;
    #pragma unroll 2
    for (int k = 0; k < 8; k++) {
        int q = q0 + k * 256;
        float xd = __fdiv_rn((float)q, 65535.0f);   // exact match of ref dequant
        float lg = mlp_eval(xd - 0.5f, w);
        float ug = mlp_eval(xd + 0.5f, w);
        float lik = fmaxf(sigf(ug) - sigf(lg), 1e-9f);
        lt[q] = lik;
        if (c == 0) g_xd[q] = xd;
    }
}

// ---------------- kernel 4: quantize + gather ----------------
// 12288 blocks x 256 threads x 8 elements (2 float4 per thread);
// each block covers 2048 contiguous elements of one (b,c) plane.
__global__ void __launch_bounds__(256) k_gather(const float* __restrict__ x,
                                                float* __restrict__ out) {
    const int base = blockIdx.x * 2048;
    const int c = (base >> 14) % C_;
    const int s = base / CHW_;

    const float qs = g_qs[s];
    const float qo = g_qo[s];
    const float* __restrict__ lt = g_lik + (size_t)c * NQ_;
    float* __restrict__ outL = out + NTOT_;
    const int t = threadIdx.x;

    const float4* xv = reinterpret_cast<const float4*>(x + base);
    float4* ov = reinterpret_cast<float4*>(out + base);
    float4* lv = reinterpret_cast<float4*>(outL + base);

    #pragma unroll
    for (int k = 0; k < 2; k++) {
        float4 v = __ldg(xv + t + k * 256);
        int q0 = min(max(__float2int_rn(fmaf(v.x, qs, qo)), 0), 65535);
        int q1 = min(max(__float2int_rn(fmaf(v.y, qs, qo)), 0), 65535);
        int q2 = min(max(__float2int_rn(fmaf(v.z, qs, qo)), 0), 65535);
        int q3 = min(max(__float2int_rn(fmaf(v.w, qs, qo)), 0), 65535);
        float4 o, l;
        o.x = g_xd[q0]; o.y = g_xd[q1]; o.z = g_xd[q2]; o.w = g_xd[q3];
        l.x = __ldg(lt + q0); l.y = __ldg(lt + q1);
        l.z = __ldg(lt + q2); l.w = __ldg(lt + q3);
        ov[t + k * 256] = o;
        lv[t + k * 256] = l;
    }
}

// ---------------- host launcher ----------------
extern "C" void kernel_launch(void* const* d_in, const int* in_sizes, int n_in,
                              void* d_out, int out_size) {
    const float* x = (const float*)d_in[0];
    const float *m[5], *bb[5], *ff[4];
    if (n_in >= 15 && in_sizes[2] == 1728) {
        for (int i = 0; i < 5; i++) { m[i]  = (const float*)d_in[1 + i];
                                      bb[i] = (const float*)d_in[6 + i]; }
        for (int i = 0; i < 4; i++)   ff[i] = (const float*)d_in[11 + i];
    } else {
        for (int i = 0; i < 5; i++) { m[i]  = (const float*)d_in[1 + 2 * i];
                                      bb[i] = (const float*)d_in[2 + 2 * i]; }
        for (int i = 0; i < 4; i++)   ff[i] = (const float*)d_in[11 + i];
    }
    float* out = (float*)d_out;

    k_init<<<1, 32>>>();
    k_minmax<<<2048, 256>>>(x);
    k_prep<<<1, 192>>>(m[0], bb[0], m[1], bb[1], m[2], bb[2], m[3], bb[3],
                       m[4], bb[4], ff[0], ff[1], ff[2], ff[3]);
    k_table<<<6144, 256>>>();
    k_gather<<<12288, 256>>>(x, out);
}

// round 3
// speedup vs baseline: 1.4706x; 1.0766x over previous
#include <cuda_runtime.h>
#include <math.h>

#define B_    8
#define C_    192
#define HW_   16384
#define CHW_  3145728
#define NTOT_ 25165824
#define NQ_   65536
#define WIN_  24576          // smem window entries (96 KB)
#define WINH_ 12288          // half window

// ---------------- device scratch (no allocations allowed) ----------------
__device__ unsigned g_min_enc[B_];
__device__ unsigned g_max_enc[B_];
__device__ float    g_qs[B_];          // per-sample quantize scale
__device__ float    g_qo[B_];          // per-sample quantize offset
__device__ int      g_w0[B_];          // per-sample window start
__device__ float    g_cw[C_ * 58];     // packed per-channel transformed weights
__device__ float    g_lik[C_ * NQ_];   // likelihood table (c, q)  ~50MB

// monotone float<->uint encoding for atomic min/max
__device__ __forceinline__ unsigned fenc(float f) {
    unsigned u = __float_as_uint(f);
    return (u & 0x80000000u) ? ~u : (u | 0x80000000u);
}
__device__ __forceinline__ float fdec(unsigned u) {
    return (u & 0x80000000u) ? __uint_as_float(u ^ 0x80000000u)
                             : __uint_as_float(~u);
}

// ---------------- kernel 0: init reduction cells ----------------
__global__ void k_init() {
    int t = threadIdx.x;
    if (t < B_) {
        g_min_enc[t] = 0xFFFFFFFFu;
        g_max_enc[t] = 0u;
    }
}

// ---------------- kernel 1: per-sample min/max ----------------
__global__ void __launch_bounds__(256) k_minmax(const float* __restrict__ x) {
    int s  = blockIdx.x >> 8;
    int jb = blockIdx.x & 255;
    const float4* xp = reinterpret_cast<const float4*>(x + (size_t)s * CHW_) + (size_t)jb * 3072;

    float mn = __int_as_float(0x7f800000);
    float mx = -mn;
    for (int i = threadIdx.x; i < 3072; i += 256) {
        float4 v = xp[i];
        mn = fminf(mn, fminf(fminf(v.x, v.y), fminf(v.z, v.w)));
        mx = fmaxf(mx, fmaxf(fmaxf(v.x, v.y), fmaxf(v.z, v.w)));
    }
    #pragma unroll
    for (int o = 16; o > 0; o >>= 1) {
        mn = fminf(mn, __shfl_xor_sync(0xffffffffu, mn, o));
        mx = fmaxf(mx, __shfl_xor_sync(0xffffffffu, mx, o));
    }
    __shared__ float smn[8], smx[8];
    int w = threadIdx.x >> 5, l = threadIdx.x & 31;
    if (l == 0) { smn[w] = mn; smx[w] = mx; }
    __syncthreads();
    if (threadIdx.x == 0) {
        mn = smn[0]; mx = smx[0];
        #pragma unroll
        for (int i = 1; i < 8; i++) { mn = fminf(mn, smn[i]); mx = fmaxf(mx, smx[i]); }
        atomicMin(&g_min_enc[s], fenc(mn));
        atomicMax(&g_max_enc[s], fenc(mx));
    }
}

// ---------------- kernel 2: precompute transformed weights ----------------
__device__ __forceinline__ float softplus_acc(float v) {
    return fmaxf(v, 0.0f) + log1pf(expf(-fabsf(v)));
}

__global__ void k_prep(const float* __restrict__ m0, const float* __restrict__ b0,
                       const float* __restrict__ m1, const float* __restrict__ b1,
                       const float* __restrict__ m2, const float* __restrict__ b2,
                       const float* __restrict__ m3, const float* __restrict__ b3,
                       const float* __restrict__ m4, const float* __restrict__ b4,
                       const float* __restrict__ f0, const float* __restrict__ f1,
                       const float* __restrict__ f2, const float* __restrict__ f3) {
    int c = threadIdx.x;
    if (c < C_) {
        float* w = &g_cw[c * 58];
        #pragma unroll
        for (int j = 0; j < 3; j++) {
            w[0 + j]  = softplus_acc(m0[c * 3 + j]);
            w[3 + j]  = b0[c * 3 + j];
            w[6 + j]  = tanhf(f0[c * 3 + j]);
            w[18 + j] = b1[c * 3 + j];
            w[21 + j] = tanhf(f1[c * 3 + j]);
            w[33 + j] = b2[c * 3 + j];
            w[36 + j] = tanhf(f2[c * 3 + j]);
            w[48 + j] = b3[c * 3 + j];
            w[51 + j] = tanhf(f3[c * 3 + j]);
            w[54 + j] = softplus_acc(m4[c * 3 + j]);
        }
        #pragma unroll
        for (int j = 0; j < 9; j++) {
            w[9  + j] = softplus_acc(m1[c * 9 + j]);
            w[24 + j] = softplus_acc(m2[c * 9 + j]);
            w[39 + j] = softplus_acc(m3[c * 9 + j]);
        }
        w[57] = b4[c];
    }
    if (threadIdx.x < B_) {
        int s = threadIdx.x;
        float mn = fdec(g_min_enc[s]);
        float mx = fdec(g_max_enc[s]);
        float denom = (mx - mn) + 1e-12f;
        float qs = __fdiv_rn(65535.0f, denom);   // q = rint((x - mn) * qs)
        float qo = -mn * qs;
        g_qs[s] = qs;
        g_qo[s] = qo;
        int w0 = (int)rintf(qo) - WINH_;
        w0 = min(max(w0, 0), NQ_ - WIN_);
        w0 &= ~3;                                 // float4 alignment
        g_w0[s] = w0;
    }
}

// ---------------- MLP with approx tanh gates, accurate final sigmoid ----------
__device__ __forceinline__ float tanha(float v) {
    float r;
    asm("tanh.approx.f32 %0, %1;" : "=f"(r) : "f"(v));
    return r;
}
__device__ __forceinline__ float sigf(float v) {
    return __fdividef(1.0f, 1.0f + __expf(-v));
}

__device__ __forceinline__ float mlp_eval(float v, const float* w) {
    float y0 = fmaf(w[0], v, w[3]);
    float y1 = fmaf(w[1], v, w[4]);
    float y2 = fmaf(w[2], v, w[5]);
    y0 = fmaf(w[6], tanha(y0), y0);
    y1 = fmaf(w[7], tanha(y1), y1);
    y2 = fmaf(w[8], tanha(y2), y2);
    #pragma unroll
    for (int L = 0; L < 3; L++) {
        int WO = 9 + L * 15, BO = WO + 9, TO = WO + 12;
        float z0 = fmaf(w[WO + 0], y0, fmaf(w[WO + 1], y1, fmaf(w[WO + 2], y2, w[BO + 0])));
        float z1 = fmaf(w[WO + 3], y0, fmaf(w[WO + 4], y1, fmaf(w[WO + 5], y2, w[BO + 1])));
        float z2 = fmaf(w[WO + 6], y0, fmaf(w[WO + 7], y1, fmaf(w[WO + 8], y2, w[BO + 2])));
        y0 = fmaf(w[TO + 0], tanha(z0), z0);
        y1 = fmaf(w[TO + 1], tanha(z1), z1);
        y2 = fmaf(w[TO + 2], tanha(z2), z2);
    }
    return fmaf(w[54], y0, fmaf(w[55], y1, fmaf(w[56], y2, w[57])));
}

// ---------------- kernel 3: build (c, q) likelihood table ----------------
__global__ void __launch_bounds__(256) k_table() {
    const int c  = blockIdx.x >> 5;
    const int q0 = ((blockIdx.x & 31) << 11) + threadIdx.x;

    float w[58];
    const float* cw = g_cw + c * 58;
    #pragma unroll
    for (int i = 0; i < 58; i++) w[i] = __ldg(cw + i);

    float* lt = g_lik + (size_t)c * NQ_;
    #pragma unroll 2
    for (int k = 0; k < 8; k++) {
        int q = q0 + k * 256;
        float xd = __fdiv_rn((float)q, 65535.0f);
        float lg = mlp_eval(xd - 0.5f, w);
        float ug = mlp_eval(xd + 0.5f, w);
        lt[q] = fmaxf(sigf(ug) - sigf(lg), 1e-9f);
    }
}

// ---------------- kernel 4: quantize + gather (smem window) ----------------
// 1536 blocks = (s, c) planes; 256 threads; 16384 elements/block.
// 96 KB smem window of the channel's table centered on q(x=0).
__global__ void __launch_bounds__(256) k_gather(const float* __restrict__ x,
                                                float* __restrict__ out) {
    extern __shared__ float sw[];
    const int c = blockIdx.x % C_;
    const int s = blockIdx.x / C_;
    const size_t base = (size_t)s * CHW_ + (size_t)c * HW_;

    const float qs = g_qs[s];
    const float qo = g_qo[s];
    const int   w0 = g_w0[s];
    const float* __restrict__ lt = g_lik + (size_t)c * NQ_;
    const int t = threadIdx.x;

    // stage table window into smem
    {
        const float4* src = reinterpret_cast<const float4*>(lt + w0);
        float4* dst = reinterpret_cast<float4*>(sw);
        #pragma unroll
        for (int i = 0; i < WIN_ / 4 / 256; i++)
            dst[t + i * 256] = __ldg(src + t + i * 256);
    }
    __syncthreads();

    const float4* xv = reinterpret_cast<const float4*>(x + base);
    float4* ov = reinterpret_cast<float4*>(out + base);
    float4* lv = reinterpret_cast<float4*>(out + NTOT_ + base);
    const float rq = 1.0f / 65535.0f;

    #pragma unroll 4
    for (int it = 0; it < 16; it++) {
        int i = t + it * 256;
        float4 v = __ldg(xv + i);
        int q0 = min(max(__float2int_rn(fmaf(v.x, qs, qo)), 0), 65535);
        int q1 = min(max(__float2int_rn(fmaf(v.y, qs, qo)), 0), 65535);
        int q2 = min(max(__float2int_rn(fmaf(v.z, qs, qo)), 0), 65535);
        int q3 = min(max(__float2int_rn(fmaf(v.w, qs, qo)), 0), 65535);
        float4 o, l;
        o.x = (float)q0 * rq; o.y = (float)q1 * rq;
        o.z = (float)q2 * rq; o.w = (float)q3 * rq;
        unsigned u0 = (unsigned)(q0 - w0), u1 = (unsigned)(q1 - w0);
        unsigned u2 = (unsigned)(q2 - w0), u3 = (unsigned)(q3 - w0);
        l.x = (u0 < WIN_) ? sw[u0] : __ldg(lt + q0);
        l.y = (u1 < WIN_) ? sw[u1] : __ldg(lt + q1);
        l.z = (u2 < WIN_) ? sw[u2] : __ldg(lt + q2);
        l.w = (u3 < WIN_) ? sw[u3] : __ldg(lt + q3);
        ov[i] = o;
        lv[i] = l;
    }
}

// ---------------- host launcher ----------------
extern "C" void kernel_launch(void* const* d_in, const int* in_sizes, int n_in,
                              void* d_out, int out_size) {
    const float* x = (const float*)d_in[0];
    const float *m[5], *bb[5], *ff[4];
    if (n_in >= 15 && in_sizes[2] == 1728) {
        for (int i = 0; i < 5; i++) { m[i]  = (const float*)d_in[1 + i];
                                      bb[i] = (const float*)d_in[6 + i]; }
        for (int i = 0; i < 4; i++)   ff[i] = (const float*)d_in[11 + i];
    } else {
        for (int i = 0; i < 5; i++) { m[i]  = (const float*)d_in[1 + 2 * i];
                                      bb[i] = (const float*)d_in[2 + 2 * i]; }
        for (int i = 0; i < 4; i++)   ff[i] = (const float*)d_in[11 + i];
    }
    float* out = (float*)d_out;

    static int smem_set = 0;
    if (!smem_set) {
        cudaFuncSetAttribute(k_gather, cudaFuncAttributeMaxDynamicSharedMemorySize,
                             WIN_ * sizeof(float));
        smem_set = 1;
    }

    k_init<<<1, 32>>>();
    k_minmax<<<2048, 256>>>(x);
    k_prep<<<1, 192>>>(m[0], bb[0], m[1], bb[1], m[2], bb[2], m[3], bb[3],
                       m[4], bb[4], ff[0], ff[1], ff[2], ff[3]);
    k_table<<<6144, 256>>>();
    k_gather<<<1536, 256, WIN_ * sizeof(float)>>>(x, out);
}

// round 4
// speedup vs baseline: 1.6431x; 1.1173x over previous
#include <cuda_runtime.h>
#include <math.h>

#define B_    8
#define C_    192
#define HW_   16384
#define CHW_  3145728
#define NTOT_ 25165824
#define NQ_   65536
#define WIN_  24576          // smem window entries (96 KB)
#define WINH_ 12288          // half window

typedef unsigned long long u64;

// ---------------- device scratch (no allocations allowed) ----------------
__device__ unsigned g_min_enc[B_];
__device__ unsigned g_max_enc[B_];
__device__ float    g_qs[B_];          // per-sample quantize scale
__device__ float    g_qo[B_];          // per-sample quantize offset
__device__ int      g_w0[B_];          // per-sample window start
__device__ float    g_cw[C_ * 58];     // packed per-channel transformed weights
__device__ float    g_lik[C_ * NQ_];   // likelihood table (c, q)  ~50MB

// monotone float<->uint encoding for atomic min/max
__device__ __forceinline__ unsigned fenc(float f) {
    unsigned u = __float_as_uint(f);
    return (u & 0x80000000u) ? ~u : (u | 0x80000000u);
}
__device__ __forceinline__ float fdec(unsigned u) {
    return (u & 0x80000000u) ? __uint_as_float(u ^ 0x80000000u)
                             : __uint_as_float(~u);
}

// ---------------- kernel 0: init reduction cells ----------------
__global__ void k_init() {
    int t = threadIdx.x;
    if (t < B_) {
        g_min_enc[t] = 0xFFFFFFFFu;
        g_max_enc[t] = 0u;
    }
}

// ---------------- kernel 1: per-sample min/max ----------------
__global__ void __launch_bounds__(256) k_minmax(const float* __restrict__ x) {
    int s  = blockIdx.x >> 8;
    int jb = blockIdx.x & 255;
    const float4* xp = reinterpret_cast<const float4*>(x + (size_t)s * CHW_) + (size_t)jb * 3072;

    float mn = __int_as_float(0x7f800000);
    float mx = -mn;
    for (int i = threadIdx.x; i < 3072; i += 256) {
        float4 v = xp[i];
        mn = fminf(mn, fminf(fminf(v.x, v.y), fminf(v.z, v.w)));
        mx = fmaxf(mx, fmaxf(fmaxf(v.x, v.y), fmaxf(v.z, v.w)));
    }
    #pragma unroll
    for (int o = 16; o > 0; o >>= 1) {
        mn = fminf(mn, __shfl_xor_sync(0xffffffffu, mn, o));
        mx = fmaxf(mx, __shfl_xor_sync(0xffffffffu, mx, o));
    }
    __shared__ float smn[8], smx[8];
    int w = threadIdx.x >> 5, l = threadIdx.x & 31;
    if (l == 0) { smn[w] = mn; smx[w] = mx; }
    __syncthreads();
    if (threadIdx.x == 0) {
        mn = smn[0]; mx = smx[0];
        #pragma unroll
        for (int i = 1; i < 8; i++) { mn = fminf(mn, smn[i]); mx = fmaxf(mx, smx[i]); }
        atomicMin(&g_min_enc[s], fenc(mn));
        atomicMax(&g_max_enc[s], fenc(mx));
    }
}

// ---------------- kernel 2: precompute transformed weights ----------------
__device__ __forceinline__ float softplus_acc(float v) {
    return fmaxf(v, 0.0f) + log1pf(expf(-fabsf(v)));
}

__global__ void k_prep(const float* __restrict__ m0, const float* __restrict__ b0,
                       const float* __restrict__ m1, const float* __restrict__ b1,
                       const float* __restrict__ m2, const float* __restrict__ b2,
                       const float* __restrict__ m3, const float* __restrict__ b3,
                       const float* __restrict__ m4, const float* __restrict__ b4,
                       const float* __restrict__ f0, const float* __restrict__ f1,
                       const float* __restrict__ f2, const float* __restrict__ f3) {
    int c = threadIdx.x;
    if (c < C_) {
        float* w = &g_cw[c * 58];
        #pragma unroll
        for (int j = 0; j < 3; j++) {
            w[0 + j]  = softplus_acc(m0[c * 3 + j]);
            w[3 + j]  = b0[c * 3 + j];
            w[6 + j]  = tanhf(f0[c * 3 + j]);
            w[18 + j] = b1[c * 3 + j];
            w[21 + j] = tanhf(f1[c * 3 + j]);
            w[33 + j] = b2[c * 3 + j];
            w[36 + j] = tanhf(f2[c * 3 + j]);
            w[48 + j] = b3[c * 3 + j];
            w[51 + j] = tanhf(f3[c * 3 + j]);
            w[54 + j] = softplus_acc(m4[c * 3 + j]);
        }
        #pragma unroll
        for (int j = 0; j < 9; j++) {
            w[9  + j] = softplus_acc(m1[c * 9 + j]);
            w[24 + j] = softplus_acc(m2[c * 9 + j]);
            w[39 + j] = softplus_acc(m3[c * 9 + j]);
        }
        w[57] = b4[c];
    }
    if (threadIdx.x < B_) {
        int s = threadIdx.x;
        float mn = fdec(g_min_enc[s]);
        float mx = fdec(g_max_enc[s]);
        float denom = (mx - mn) + 1e-12f;
        float qs = __fdiv_rn(65535.0f, denom);   // q = rint((x - mn) * qs)
        float qo = -mn * qs;
        g_qs[s] = qs;
        g_qo[s] = qo;
        int w0 = (int)rintf(qo) - WINH_;
        w0 = min(max(w0, 0), NQ_ - WIN_);
        w0 &= ~3;                                 // float4 alignment
        g_w0[s] = w0;
    }
}

// ---------------- packed f32x2 helpers (sm_103a FFMA2) ----------------
__device__ __forceinline__ u64 pk2(float a, float b) {
    u64 r; asm("mov.b64 %0, {%1, %2};" : "=l"(r) : "f"(a), "f"(b)); return r;
}
__device__ __forceinline__ void unpk(u64 v, float& a, float& b) {
    asm("mov.b64 {%0, %1}, %2;" : "=f"(a), "=f"(b) : "l"(v));
}
__device__ __forceinline__ u64 fma2(u64 a, u64 b, u64 c) {
    u64 d; asm("fma.rn.f32x2 %0, %1, %2, %3;" : "=l"(d) : "l"(a), "l"(b), "l"(c));
    return d;
}
// gate: y = z + t * tanh(z), tanh via f16x2 MUFU (both lanes in one op)
__device__ __forceinline__ u64 gate2(u64 z, u64 t2) {
    float zl, zu;
    unpk(z, zl, zu);
    unsigned h;
    asm("cvt.rn.f16x2.f32 %0, %1, %2;" : "=r"(h) : "f"(zu), "f"(zl)); // lo=zl, hi=zu
    asm("tanh.approx.f16x2 %0, %1;" : "=r"(h) : "r"(h));
    float tl, tu;
    asm("{\n\t.reg .b16 lo, hi;\n\tmov.b32 {lo, hi}, %2;\n\t"
        "cvt.f32.f16 %0, lo;\n\tcvt.f32.f16 %1, hi;\n\t}"
        : "=f"(tl), "=f"(tu) : "r"(h));
    return fma2(t2, pk2(tl, tu), z);
}
__device__ __forceinline__ float sigf(float v) {
    return __fdividef(1.0f, 1.0f + __expf(-v));
}

// packed MLP: v = (lower, upper) of one q; returns packed final logits
// W: 33 packed matmul weights, Bb: 13 packed biases, T: 12 packed gate weights
__device__ __forceinline__ u64 mlp2p(u64 v, const u64* W, const u64* Bb, const u64* T) {
    u64 y0 = fma2(W[0], v, Bb[0]);
    u64 y1 = fma2(W[1], v, Bb[1]);
    u64 y2 = fma2(W[2], v, Bb[2]);
    y0 = gate2(y0, T[0]);
    y1 = gate2(y1, T[1]);
    y2 = gate2(y2, T[2]);
    #pragma unroll
    for (int L = 0; L < 3; L++) {
        const u64* Wl = W + 3 + L * 9;
        const u64* Bl = Bb + 3 + L * 3;
        const u64* Tl = T + 3 + L * 3;
        u64 z0 = fma2(Wl[0], y0, fma2(Wl[1], y1, fma2(Wl[2], y2, Bl[0])));
        u64 z1 = fma2(Wl[3], y0, fma2(Wl[4], y1, fma2(Wl[5], y2, Bl[1])));
        u64 z2 = fma2(Wl[6], y0, fma2(Wl[7], y1, fma2(Wl[8], y2, Bl[2])));
        y0 = gate2(z0, Tl[0]);
        y1 = gate2(z1, Tl[1]);
        y2 = gate2(z2, Tl[2]);
    }
    return fma2(W[30], y0, fma2(W[31], y1, fma2(W[32], y2, Bb[12])));
}

// ---------------- kernel 3: build (c, q) likelihood table ----------------
// 6144 blocks (32 per channel) x 256 threads; thread does 4 iterations x 2 q's (ILP)
__global__ void __launch_bounds__(256) k_table() {
    const int c  = blockIdx.x >> 5;
    const int q0 = ((blockIdx.x & 31) << 11) + threadIdx.x;

    const float* cw = g_cw + c * 58;
    float w[58];
    #pragma unroll
    for (int i = 0; i < 58; i++) w[i] = __ldg(cw + i);

    // broadcast-pack weights once
    u64 W[33], Bb[13], T[12];
    #pragma unroll
    for (int j = 0; j < 3; j++) {
        W[j]      = pk2(w[j], w[j]);               // W0
        W[30 + j] = pk2(w[54 + j], w[54 + j]);     // W4
        Bb[j]     = pk2(w[3 + j], w[3 + j]);       // B0
        T[j]      = pk2(w[6 + j], w[6 + j]);       // T0
    }
    #pragma unroll
    for (int L = 0; L < 3; L++) {
        #pragma unroll
        for (int j = 0; j < 9; j++)
            W[3 + L * 9 + j] = pk2(w[9 + L * 15 + j], w[9 + L * 15 + j]);
        #pragma unroll
        for (int j = 0; j < 3; j++) {
            Bb[3 + L * 3 + j] = pk2(w[18 + L * 15 + j], w[18 + L * 15 + j]);
            T[3 + L * 3 + j]  = pk2(w[21 + L * 15 + j], w[21 + L * 15 + j]);
        }
    }
    Bb[12] = pk2(w[57], w[57]);

    float* lt = g_lik + (size_t)c * NQ_;
    const float rq = 1.0f / 65535.0f;

    #pragma unroll
    for (int k = 0; k < 4; k++) {
        int qa = q0 + k * 256;
        int qb = qa + 1024;
        float xa = (float)qa * rq;
        float xb = (float)qb * rq;
        u64 la = mlp2p(pk2(xa - 0.5f, xa + 0.5f), W, Bb, T);
        u64 lb = mlp2p(pk2(xb - 0.5f, xb + 0.5f), W, Bb, T);
        float lal, lau, lbl, lbu;
        unpk(la, lal, lau);
        unpk(lb, lbl, lbu);
        lt[qa] = fmaxf(sigf(lau) - sigf(lal), 1e-9f);
        lt[qb] = fmaxf(sigf(lbu) - sigf(lbl), 1e-9f);
    }
}

// ---------------- kernel 4: quantize + gather (smem window) ----------------
// 1536 blocks = (s, c) planes; 256 threads; 16384 elements/block.
// All 16 x-loads issued to registers up front (deep MLP), fill overlaps.
__global__ void __launch_bounds__(256, 2) k_gather(const float* __restrict__ x,
                                                   float* __restrict__ out) {
    extern __shared__ float sw[];
    const int c = blockIdx.x % C_;
    const int s = blockIdx.x / C_;
    const size_t base = (size_t)s * CHW_ + (size_t)c * HW_;

    const float qs = g_qs[s];
    const float qo = g_qo[s];
    const int   w0 = g_w0[s];
    const float* __restrict__ lt = g_lik + (size_t)c * NQ_;
    const int t = threadIdx.x;

    // 1) issue all x loads first (40+ LDGs in flight per warp with fill)
    const float4* xp = reinterpret_cast<const float4*>(x + base);
    float4 xv[16];
    #pragma unroll
    for (int i = 0; i < 16; i++) xv[i] = __ldg(xp + t + i * 256);

    // 2) stage table window into smem (overlaps x-load latency)
    {
        const float4* src = reinterpret_cast<const float4*>(lt + w0);
        float4* dst = reinterpret_cast<float4*>(sw);
        #pragma unroll
        for (int i = 0; i < WIN_ / 4 / 256; i++)
            dst[t + i * 256] = __ldg(src + t + i * 256);
    }
    __syncthreads();

    float4* ov = reinterpret_cast<float4*>(out + base);
    float4* lv = reinterpret_cast<float4*>(out + NTOT_ + base);
    const float rq = 1.0f / 65535.0f;

    #pragma unroll 4
    for (int i = 0; i < 16; i++) {
        float4 v = xv[i];
        int q0 = min(max(__float2int_rn(fmaf(v.x, qs, qo)), 0), 65535);
        int q1 = min(max(__float2int_rn(fmaf(v.y, qs, qo)), 0), 65535);
        int q2 = min(max(__float2int_rn(fmaf(v.z, qs, qo)), 0), 65535);
        int q3 = min(max(__float2int_rn(fmaf(v.w, qs, qo)), 0), 65535);
        float4 o, l;
        o.x = (float)q0 * rq; o.y = (float)q1 * rq;
        o.z = (float)q2 * rq; o.w = (float)q3 * rq;
        unsigned u0 = (unsigned)(q0 - w0), u1 = (unsigned)(q1 - w0);
        unsigned u2 = (unsigned)(q2 - w0), u3 = (unsigned)(q3 - w0);
        l.x = (u0 < WIN_) ? sw[u0] : __ldg(lt + q0);
        l.y = (u1 < WIN_) ? sw[u1] : __ldg(lt + q1);
        l.z = (u2 < WIN_) ? sw[u2] : __ldg(lt + q2);
        l.w = (u3 < WIN_) ? sw[u3] : __ldg(lt + q3);
        ov[t + i * 256] = o;
        lv[t + i * 256] = l;
    }
}

// ---------------- host launcher ----------------
extern "C" void kernel_launch(void* const* d_in, const int* in_sizes, int n_in,
                              void* d_out, int out_size) {
    const float* x = (const float*)d_in[0];
    const float *m[5], *bb[5], *ff[4];
    if (n_in >= 15 && in_sizes[2] == 1728) {
        for (int i = 0; i < 5; i++) { m[i]  = (const float*)d_in[1 + i];
                                      bb[i] = (const float*)d_in[6 + i]; }
        for (int i = 0; i < 4; i++)   ff[i] = (const float*)d_in[11 + i];
    } else {
        for (int i = 0; i < 5; i++) { m[i]  = (const float*)d_in[1 + 2 * i];
                                      bb[i] = (const float*)d_in[2 + 2 * i]; }
        for (int i = 0; i < 4; i++)   ff[i] = (const float*)d_in[11 + i];
    }
    float* out = (float*)d_out;

    static int smem_set = 0;
    if (!smem_set) {
        cudaFuncSetAttribute(k_gather, cudaFuncAttributeMaxDynamicSharedMemorySize,
                             WIN_ * sizeof(float));
        smem_set = 1;
    }

    k_init<<<1, 32>>>();
    k_minmax<<<2048, 256>>>(x);
    k_prep<<<1, 192>>>(m[0], bb[0], m[1], bb[1], m[2], bb[2], m[3], bb[3],
                       m[4], bb[4], ff[0], ff[1], ff[2], ff[3]);
    k_table<<<6144, 256>>>();
    k_gather<<<1536, 256, WIN_ * sizeof(float)>>>(x, out);
}

// round 5
// speedup vs baseline: 1.8130x; 1.1034x over previous
#include <cuda_runtime.h>
#include <math.h>

#define B_    8
#define C_    192
#define HW_   16384
#define CHW_  3145728
#define NTOT_ 25165824
#define NQ_   65536
#define WIN_  24576          // smem window entries (96 KB)
#define WINH_ 12288          // half window

typedef unsigned long long u64;

// ---------------- device scratch (no allocations allowed) ----------------
__device__ unsigned g_min_enc[B_];
__device__ unsigned g_max_enc[B_];
__device__ float    g_qs[B_];          // per-sample quantize scale
__device__ float    g_qo[B_];          // per-sample quantize offset
__device__ int      g_w0[B_];          // per-sample window start
__device__ float    g_cw[C_ * 58];     // packed per-channel transformed weights
__device__ float    g_lik[C_ * NQ_];   // likelihood table (c, q)  ~50MB

// monotone float<->uint encoding for atomic min/max
__device__ __forceinline__ unsigned fenc(float f) {
    unsigned u = __float_as_uint(f);
    return (u & 0x80000000u) ? ~u : (u | 0x80000000u);
}
__device__ __forceinline__ float fdec(unsigned u) {
    return (u & 0x80000000u) ? __uint_as_float(u ^ 0x80000000u)
                             : __uint_as_float(~u);
}

// ---------------- kernel 0: init reduction cells ----------------
__global__ void k_init() {
    int t = threadIdx.x;
    if (t < B_) {
        g_min_enc[t] = 0xFFFFFFFFu;
        g_max_enc[t] = 0u;
    }
}

// ---------------- kernel 1: per-sample min/max ----------------
__global__ void __launch_bounds__(256) k_minmax(const float* __restrict__ x) {
    int s  = blockIdx.x >> 8;
    int jb = blockIdx.x & 255;
    const float4* xp = reinterpret_cast<const float4*>(x + (size_t)s * CHW_) + (size_t)jb * 3072;

    float mn = __int_as_float(0x7f800000);
    float mx = -mn;
    for (int i = threadIdx.x; i < 3072; i += 256) {
        float4 v = xp[i];
        mn = fminf(mn, fminf(fminf(v.x, v.y), fminf(v.z, v.w)));
        mx = fmaxf(mx, fmaxf(fmaxf(v.x, v.y), fmaxf(v.z, v.w)));
    }
    #pragma unroll
    for (int o = 16; o > 0; o >>= 1) {
        mn = fminf(mn, __shfl_xor_sync(0xffffffffu, mn, o));
        mx = fmaxf(mx, __shfl_xor_sync(0xffffffffu, mx, o));
    }
    __shared__ float smn[8], smx[8];
    int w = threadIdx.x >> 5, l = threadIdx.x & 31;
    if (l == 0) { smn[w] = mn; smx[w] = mx; }
    __syncthreads();
    if (threadIdx.x == 0) {
        mn = smn[0]; mx = smx[0];
        #pragma unroll
        for (int i = 1; i < 8; i++) { mn = fminf(mn, smn[i]); mx = fmaxf(mx, smx[i]); }
        atomicMin(&g_min_enc[s], fenc(mn));
        atomicMax(&g_max_enc[s], fenc(mx));
    }
}

// ---------------- kernel 2: precompute transformed weights ----------------
__device__ __forceinline__ float softplus_acc(float v) {
    return fmaxf(v, 0.0f) + log1pf(expf(-fabsf(v)));
}

__global__ void k_prep(const float* __restrict__ m0, const float* __restrict__ b0,
                       const float* __restrict__ m1, const float* __restrict__ b1,
                       const float* __restrict__ m2, const float* __restrict__ b2,
                       const float* __restrict__ m3, const float* __restrict__ b3,
                       const float* __restrict__ m4, const float* __restrict__ b4,
                       const float* __restrict__ f0, const float* __restrict__ f1,
                       const float* __restrict__ f2, const float* __restrict__ f3) {
    int c = threadIdx.x;
    if (c < C_) {
        float* w = &g_cw[c * 58];
        #pragma unroll
        for (int j = 0; j < 3; j++) {
            w[0 + j]  = softplus_acc(m0[c * 3 + j]);
            w[3 + j]  = b0[c * 3 + j];
            w[6 + j]  = tanhf(f0[c * 3 + j]);
            w[18 + j] = b1[c * 3 + j];
            w[21 + j] = tanhf(f1[c * 3 + j]);
            w[33 + j] = b2[c * 3 + j];
            w[36 + j] = tanhf(f2[c * 3 + j]);
            w[48 + j] = b3[c * 3 + j];
            w[51 + j] = tanhf(f3[c * 3 + j]);
            w[54 + j] = softplus_acc(m4[c * 3 + j]);
        }
        #pragma unroll
        for (int j = 0; j < 9; j++) {
            w[9  + j] = softplus_acc(m1[c * 9 + j]);
            w[24 + j] = softplus_acc(m2[c * 9 + j]);
            w[39 + j] = softplus_acc(m3[c * 9 + j]);
        }
        w[57] = b4[c];
    }
    if (threadIdx.x < B_) {
        int s = threadIdx.x;
        float mn = fdec(g_min_enc[s]);
        float mx = fdec(g_max_enc[s]);
        float denom = (mx - mn) + 1e-12f;
        float qs = __fdiv_rn(65535.0f, denom);   // q = rint((x - mn) * qs)
        float qo = -mn * qs;
        g_qs[s] = qs;
        g_qo[s] = qo;
        int w0 = (int)rintf(qo) - WINH_;
        w0 = min(max(w0, 0), NQ_ - WIN_);
        w0 &= ~3;                                 // float4 alignment
        g_w0[s] = w0;
    }
}

// ---------------- packed f32x2 helpers (sm_103a FFMA2) ----------------
__device__ __forceinline__ u64 pk2(float a, float b) {
    u64 r; asm("mov.b64 %0, {%1, %2};" : "=l"(r) : "f"(a), "f"(b)); return r;
}
__device__ __forceinline__ void unpk(u64 v, float& a, float& b) {
    asm("mov.b64 {%0, %1}, %2;" : "=f"(a), "=f"(b) : "l"(v));
}
__device__ __forceinline__ u64 fma2(u64 a, u64 b, u64 c) {
    u64 d; asm("fma.rn.f32x2 %0, %1, %2, %3;" : "=l"(d) : "l"(a), "l"(b), "l"(c));
    return d;
}
// gate: y = z + t * tanh(z), tanh via f16x2 MUFU (both lanes in one op)
__device__ __forceinline__ u64 gate2(u64 z, u64 t2) {
    float zl, zu;
    unpk(z, zl, zu);
    unsigned h;
    asm("cvt.rn.f16x2.f32 %0, %1, %2;" : "=r"(h) : "f"(zu), "f"(zl)); // lo=zl, hi=zu
    asm("tanh.approx.f16x2 %0, %1;" : "=r"(h) : "r"(h));
    float tl, tu;
    asm("{\n\t.reg .b16 lo, hi;\n\tmov.b32 {lo, hi}, %2;\n\t"
        "cvt.f32.f16 %0, lo;\n\tcvt.f32.f16 %1, hi;\n\t}"
        : "=f"(tl), "=f"(tu) : "r"(h));
    return fma2(t2, pk2(tl, tu), z);
}
__device__ __forceinline__ float sigf(float v) {
    return __fdividef(1.0f, 1.0f + __expf(-v));
}

// dual-q packed MLP: va/vb = packed (lower, upper) for two q's.
// Weights live in smem (broadcast LDS.64), loaded once per use-pair.
__device__ __forceinline__ void mlp_dual(u64 va, u64 vb, const u64* __restrict__ sW,
                                         u64& ra, u64& rb) {
    u64 w0 = sW[0], w1 = sW[1], w2 = sW[2];
    u64 bb0 = sW[3], bb1 = sW[4], bb2 = sW[5];
    u64 ya0 = fma2(w0, va, bb0), yb0 = fma2(w0, vb, bb0);
    u64 ya1 = fma2(w1, va, bb1), yb1 = fma2(w1, vb, bb1);
    u64 ya2 = fma2(w2, va, bb2), yb2 = fma2(w2, vb, bb2);
    u64 t0 = sW[6], t1 = sW[7], t2 = sW[8];
    ya0 = gate2(ya0, t0); yb0 = gate2(yb0, t0);
    ya1 = gate2(ya1, t1); yb1 = gate2(yb1, t1);
    ya2 = gate2(ya2, t2); yb2 = gate2(yb2, t2);
    #pragma unroll
    for (int L = 0; L < 3; L++) {
        const u64* Wl = sW + 9 + L * 15;
        u64 m0 = Wl[0], m1 = Wl[1], m2 = Wl[2];
        u64 m3 = Wl[3], m4 = Wl[4], m5 = Wl[5];
        u64 m6 = Wl[6], m7 = Wl[7], m8 = Wl[8];
        u64 c0 = Wl[9], c1 = Wl[10], c2 = Wl[11];
        u64 za0 = fma2(m0, ya0, fma2(m1, ya1, fma2(m2, ya2, c0)));
        u64 zb0 = fma2(m0, yb0, fma2(m1, yb1, fma2(m2, yb2, c0)));
        u64 za1 = fma2(m3, ya0, fma2(m4, ya1, fma2(m5, ya2, c1)));
        u64 zb1 = fma2(m3, yb0, fma2(m4, yb1, fma2(m5, yb2, c1)));
        u64 za2 = fma2(m6, ya0, fma2(m7, ya1, fma2(m8, ya2, c2)));
        u64 zb2 = fma2(m6, yb0, fma2(m7, yb1, fma2(m8, yb2, c2)));
        u64 g0 = Wl[12], g1 = Wl[13], g2 = Wl[14];
        ya0 = gate2(za0, g0); yb0 = gate2(zb0, g0);
        ya1 = gate2(za1, g1); yb1 = gate2(zb1, g1);
        ya2 = gate2(za2, g2); yb2 = gate2(zb2, g2);
    }
    u64 f0 = sW[54], f1 = sW[55], f2 = sW[56], f3 = sW[57];
    ra = fma2(f0, ya0, fma2(f1, ya1, fma2(f2, ya2, f3)));
    rb = fma2(f0, yb0, fma2(f1, yb1, fma2(f2, yb2, f3)));
}

// ---------------- kernel 3: build (c, q) likelihood table ----------------
// 6144 blocks (32 per channel) x 256 threads; thread does 4 dual-q iterations.
__global__ void __launch_bounds__(256) k_table() {
    __shared__ u64 sW[58];
    const int c  = blockIdx.x >> 5;
    const int q0 = ((blockIdx.x & 31) << 11) + threadIdx.x;

    if (threadIdx.x < 58) {
        float wv = g_cw[c * 58 + threadIdx.x];
        sW[threadIdx.x] = pk2(wv, wv);
    }
    __syncthreads();

    float* lt = g_lik + (size_t)c * NQ_;
    const float rq = 1.0f / 65535.0f;

    #pragma unroll
    for (int k = 0; k < 4; k++) {
        int qa = q0 + k * 256;
        int qb = qa + 1024;
        float xa = (float)qa * rq;
        float xb = (float)qb * rq;
        u64 la, lb;
        mlp_dual(pk2(xa - 0.5f, xa + 0.5f), pk2(xb - 0.5f, xb + 0.5f), sW, la, lb);
        float lal, lau, lbl, lbu;
        unpk(la, lal, lau);
        unpk(lb, lbl, lbu);
        lt[qa] = fmaxf(sigf(lau) - sigf(lal), 1e-9f);
        lt[qb] = fmaxf(sigf(lbu) - sigf(lbl), 1e-9f);
    }
}

// ---------------- kernel 4: quantize + gather (smem window) ----------------
// 1536 blocks = (s, c) planes; 256 threads; 16384 elements/block,
// processed as 2 chunks of 32 elements/thread with batched miss prefetch.
struct GatherCtx {
    const float* lt;
    float* sw;
    float4* ov;
    float4* lv;
    float qs, qo, rq;
    int w0, t;
};

__device__ __forceinline__ void gather_chunk(const float4* __restrict__ xp,
                                             int off4, const GatherCtx& g) {
    float4 xv[8];
    #pragma unroll
    for (int i = 0; i < 8; i++) xv[i] = __ldg(xp + off4 + g.t + i * 256);

    int u[32];
    #pragma unroll
    for (int i = 0; i < 8; i++) {
        float4 v = xv[i];
        u[4 * i + 0] = min(max(__float2int_rn(fmaf(v.x, g.qs, g.qo)), 0), 65535) - g.w0;
        u[4 * i + 1] = min(max(__float2int_rn(fmaf(v.y, g.qs, g.qo)), 0), 65535) - g.w0;
        u[4 * i + 2] = min(max(__float2int_rn(fmaf(v.z, g.qs, g.qo)), 0), 65535) - g.w0;
        u[4 * i + 3] = min(max(__float2int_rn(fmaf(v.w, g.qs, g.qo)), 0), 65535) - g.w0;
    }

    // batched predicated miss loads (all in flight before first use)
    float ms[32];
    #pragma unroll
    for (int j = 0; j < 32; j++) {
        ms[j] = ((unsigned)u[j] >= WIN_) ? __ldg(g.lt + (u[j] + g.w0)) : 0.0f;
    }

    // dequantized output
    #pragma unroll
    for (int i = 0; i < 8; i++) {
        float4 o;
        o.x = (float)(u[4 * i + 0] + g.w0) * g.rq;
        o.y = (float)(u[4 * i + 1] + g.w0) * g.rq;
        o.z = (float)(u[4 * i + 2] + g.w0) * g.rq;
        o.w = (float)(u[4 * i + 3] + g.w0) * g.rq;
        g.ov[off4 + g.t + i * 256] = o;
    }

    // likelihood via smem window (miss fallback already resident)
    #pragma unroll
    for (int i = 0; i < 8; i++) {
        float4 l;
        unsigned u0 = (unsigned)u[4 * i + 0], u1 = (unsigned)u[4 * i + 1];
        unsigned u2 = (unsigned)u[4 * i + 2], u3 = (unsigned)u[4 * i + 3];
        l.x = (u0 < WIN_) ? g.sw[u0] : ms[4 * i + 0];
        l.y = (u1 < WIN_) ? g.sw[u1] : ms[4 * i + 1];
        l.z = (u2 < WIN_) ? g.sw[u2] : ms[4 * i + 2];
        l.w = (u3 < WIN_) ? g.sw[u3] : ms[4 * i + 3];
        g.lv[off4 + g.t + i * 256] = l;
    }
}

__global__ void __launch_bounds__(256, 2) k_gather(const float* __restrict__ x,
                                                   float* __restrict__ out) {
    extern __shared__ float sw[];
    const int c = blockIdx.x % C_;
    const int s = blockIdx.x / C_;
    const size_t base = (size_t)s * CHW_ + (size_t)c * HW_;

    GatherCtx g;
    g.qs = g_qs[s];
    g.qo = g_qo[s];
    g.w0 = g_w0[s];
    g.lt = g_lik + (size_t)c * NQ_;
    g.sw = sw;
    g.ov = reinterpret_cast<float4*>(out + base);
    g.lv = reinterpret_cast<float4*>(out + NTOT_ + base);
    g.rq = 1.0f / 65535.0f;
    g.t  = threadIdx.x;

    const float4* xp = reinterpret_cast<const float4*>(x + base);

    // stage table window into smem
    {
        const float4* src = reinterpret_cast<const float4*>(g.lt + g.w0);
        float4* dst = reinterpret_cast<float4*>(sw);
        #pragma unroll
        for (int i = 0; i < WIN_ / 4 / 256; i++)
            dst[g.t + i * 256] = __ldg(src + g.t + i * 256);
    }
    __syncthreads();

    gather_chunk(xp, 0, g);
    gather_chunk(xp, 2048, g);
}

// ---------------- host launcher ----------------
extern "C" void kernel_launch(void* const* d_in, const int* in_sizes, int n_in,
                              void* d_out, int out_size) {
    const float* x = (const float*)d_in[0];
    const float *m[5], *bb[5], *ff[4];
    if (n_in >= 15 && in_sizes[2] == 1728) {
        for (int i = 0; i < 5; i++) { m[i]  = (const float*)d_in[1 + i];
                                      bb[i] = (const float*)d_in[6 + i]; }
        for (int i = 0; i < 4; i++)   ff[i] = (const float*)d_in[11 + i];
    } else {
        for (int i = 0; i < 5; i++) { m[i]  = (const float*)d_in[1 + 2 * i];
                                      bb[i] = (const float*)d_in[2 + 2 * i]; }
        for (int i = 0; i < 4; i++)   ff[i] = (const float*)d_in[11 + i];
    }
    float* out = (float*)d_out;

    static int smem_set = 0;
    if (!smem_set) {
        cudaFuncSetAttribute(k_gather, cudaFuncAttributeMaxDynamicSharedMemorySize,
                             WIN_ * sizeof(float));
        smem_set = 1;
    }

    k_init<<<1, 32>>>();
    k_minmax<<<2048, 256>>>(x);
    k_prep<<<1, 192>>>(m[0], bb[0], m[1], bb[1], m[2], bb[2], m[3], bb[3],
                       m[4], bb[4], ff[0], ff[1], ff[2], ff[3]);
    k_table<<<6144, 256>>>();
    k_gather<<<1536, 256, WIN_ * sizeof(float)>>>(x, out);
}